// round 1
// baseline (speedup 1.0000x reference)
#include <cuda_runtime.h>
#include <math.h>

#define BB   256
#define NPIX 1089
#define WDIM 33
#define MDIM 272
#define CC   32
#define PADS 36
#define CH_STRIDE (35*PADS)   /* 1260 floats per padded channel */
#define CONV_THREADS 384

#define FLAG_ACT_IN 1
#define FLAG_FLIP   2
#define FLAG_ACTDER 4

// ---------------- device state (static, no allocation) ----------------
__device__ float d_P[NPIX*NPIX];
__device__ float d_PhiTb[BB*NPIX];
__device__ float d_x[BB*NPIX];
__device__ float d_z[BB*NPIX];
__device__ float d_gphi[BB*NPIX];
__device__ float d_x1[BB*CC*NPIX];
__device__ float d_x2[BB*CC*NPIX];
__device__ float d_x3[BB*CC*NPIX];
__device__ float d_g [BB*CC*NPIX];
__device__ float d_bA[BB*CC*NPIX];
__device__ float d_ngrad[BB];
__device__ float d_gamma;

// ---------------- activation (eq. 33), DELTA = 0.01 ----------------
__device__ __forceinline__ float actf(float v) {
    if (fabsf(v) > 0.01f) return fmaxf(v, 0.0f);
    return fmaf(v*v, 25.0f, fmaf(v, 0.5f, 0.0025f));   // v^2/(4d) + v/2 + d/4
}
__device__ __forceinline__ float actdf(float v) {
    if (fabsf(v) > 0.01f) return v > 0.0f ? 1.0f : 0.0f;
    return fmaf(v, 50.0f, 0.5f);                        // v/(2d) + 1/2
}

__global__ void k_init_gamma() { d_gamma = 1.0f; }

// ---------------- GEMM: P = Phi^T Phi  (1089x1089, K=272) ----------------
__global__ void k_phitphi(const float* __restrict__ Phi) {
    __shared__ float As[32][33];
    __shared__ float Bs[32][33];
    int ib = blockIdx.y * 32, jb = blockIdx.x * 32;
    int tx = threadIdx.x, ty = threadIdx.y;
    int t = ty * 16 + tx;
    float acc00 = 0.f, acc01 = 0.f, acc10 = 0.f, acc11 = 0.f;
    for (int k0 = 0; k0 < MDIM; k0 += 32) {
        for (int q = t; q < 1024; q += 256) {
            int kk = q / 32, c = q % 32;
            As[kk][c] = (k0 + kk < MDIM && ib + c < NPIX) ? Phi[(k0 + kk) * NPIX + ib + c] : 0.f;
            Bs[kk][c] = (k0 + kk < MDIM && jb + c < NPIX) ? Phi[(k0 + kk) * NPIX + jb + c] : 0.f;
        }
        __syncthreads();
        #pragma unroll
        for (int kk = 0; kk < 32; kk++) {
            float a0 = As[kk][ty*2], a1 = As[kk][ty*2+1];
            float b0 = Bs[kk][tx*2], b1 = Bs[kk][tx*2+1];
            acc00 = fmaf(a0, b0, acc00); acc01 = fmaf(a0, b1, acc01);
            acc10 = fmaf(a1, b0, acc10); acc11 = fmaf(a1, b1, acc11);
        }
        __syncthreads();
    }
    int i0 = ib + ty*2, j0 = jb + tx*2;
    if (i0     < NPIX && j0     < NPIX) d_P[(i0  ) * NPIX + j0  ] = acc00;
    if (i0     < NPIX && j0 + 1 < NPIX) d_P[(i0  ) * NPIX + j0+1] = acc01;
    if (i0 + 1 < NPIX && j0     < NPIX) d_P[(i0+1) * NPIX + j0  ] = acc10;
    if (i0 + 1 < NPIX && j0 + 1 < NPIX) d_P[(i0+1) * NPIX + j0+1] = acc11;
}

// ---------------- setup GEMMs: dst[b,j] = sum_m Phix[b,m]*B(m,j) ----------------
// tmode 0: B(m,j) = Phi[m*NPIX+j]          (PhiTb)
// tmode 1: B(m,j) = Qinit[j*MDIM+m]        (x0 = Phix @ Qinit^T)
__global__ void k_setup(const float* __restrict__ Phix, const float* __restrict__ Bsrc,
                        float* __restrict__ dst, int tmode) {
    __shared__ float As[32][33];
    __shared__ float Bs[32][33];
    int bb = blockIdx.y * 32, jb = blockIdx.x * 32;
    int tx = threadIdx.x, ty = threadIdx.y;
    int t = ty * 16 + tx;
    float acc00 = 0.f, acc01 = 0.f, acc10 = 0.f, acc11 = 0.f;
    for (int k0 = 0; k0 < MDIM; k0 += 32) {
        for (int q = t; q < 1024; q += 256) {
            int kk = q % 32, r = q / 32;
            As[kk][r] = (k0 + kk < MDIM) ? Phix[(bb + r) * MDIM + k0 + kk] : 0.f;
        }
        if (tmode == 0) {
            for (int q = t; q < 1024; q += 256) {
                int kk = q / 32, j = q % 32;
                Bs[kk][j] = (k0 + kk < MDIM && jb + j < NPIX) ? Bsrc[(k0 + kk) * NPIX + jb + j] : 0.f;
            }
        } else {
            for (int q = t; q < 1024; q += 256) {
                int kk = q % 32, j = q / 32;
                Bs[kk][j] = (k0 + kk < MDIM && jb + j < NPIX) ? Bsrc[(jb + j) * MDIM + k0 + kk] : 0.f;
            }
        }
        __syncthreads();
        #pragma unroll
        for (int kk = 0; kk < 32; kk++) {
            float a0 = As[kk][ty*2], a1 = As[kk][ty*2+1];
            float b0 = Bs[kk][tx*2], b1 = Bs[kk][tx*2+1];
            acc00 = fmaf(a0, b0, acc00); acc01 = fmaf(a0, b1, acc01);
            acc10 = fmaf(a1, b0, acc10); acc11 = fmaf(a1, b1, acc11);
        }
        __syncthreads();
    }
    int b0 = bb + ty*2, j0 = jb + tx*2;
    if (j0     < NPIX) dst[(b0  ) * NPIX + j0  ] = acc00;
    if (j0 + 1 < NPIX) dst[(b0  ) * NPIX + j0+1] = acc01;
    if (j0     < NPIX) dst[(b0+1) * NPIX + j0  ] = acc10;
    if (j0 + 1 < NPIX) dst[(b0+1) * NPIX + j0+1] = acc11;
}

// ---------------- phase GEMM: dot = src @ P ----------------
// mode 0: dst = src + |alphas[p]| * (PhiTb - dot)      (z step)
// mode 1: dst = dot - PhiTb                            (gphi, grad_r added later)
__global__ void k_gemm_phase(const float* __restrict__ src, float* __restrict__ dst,
                             const float* __restrict__ alphas, int phase, int mode) {
    __shared__ float As[32][33];
    __shared__ float Bs[32][33];
    int bb = blockIdx.y * 32, jb = blockIdx.x * 32;
    int tx = threadIdx.x, ty = threadIdx.y;
    int t = ty * 16 + tx;
    float acc00 = 0.f, acc01 = 0.f, acc10 = 0.f, acc11 = 0.f;
    for (int k0 = 0; k0 < NPIX; k0 += 32) {
        for (int q = t; q < 1024; q += 256) {
            int kk = q % 32, r = q / 32;
            As[kk][r] = (k0 + kk < NPIX) ? src[(bb + r) * NPIX + k0 + kk] : 0.f;
        }
        for (int q = t; q < 1024; q += 256) {
            int kk = q / 32, j = q % 32;
            Bs[kk][j] = (k0 + kk < NPIX && jb + j < NPIX) ? d_P[(k0 + kk) * NPIX + jb + j] : 0.f;
        }
        __syncthreads();
        #pragma unroll
        for (int kk = 0; kk < 32; kk++) {
            float a0 = As[kk][ty*2], a1 = As[kk][ty*2+1];
            float b0 = Bs[kk][tx*2], b1 = Bs[kk][tx*2+1];
            acc00 = fmaf(a0, b0, acc00); acc01 = fmaf(a0, b1, acc01);
            acc10 = fmaf(a1, b0, acc10); acc11 = fmaf(a1, b1, acc11);
        }
        __syncthreads();
    }
    int b0 = bb + ty*2, j0 = jb + tx*2;
    float alpha = fabsf(alphas[phase]);
    float accs[2][2] = {{acc00, acc01}, {acc10, acc11}};
    #pragma unroll
    for (int r = 0; r < 2; r++) {
        #pragma unroll
        for (int c = 0; c < 2; c++) {
            int b = b0 + r, j = j0 + c;
            if (j < NPIX) {
                float dot = accs[r][c];
                float ptb = d_PhiTb[b * NPIX + j];
                if (mode == 0)
                    dst[b * NPIX + j] = src[b * NPIX + j] + alpha * (ptb - dot);
                else
                    dst[b * NPIX + j] = dot - ptb;
            }
        }
    }
}

// ---------------- conv1 forward: [B,1,33,33] -> [B,32,33,33] ----------------
__global__ __launch_bounds__(CONV_THREADS) void k_conv1(
        const float* __restrict__ in, const float* __restrict__ w,
        float* __restrict__ out) {
    __shared__ float s_in[CH_STRIDE];
    __shared__ float s_w[9 * CC];       // [k][co]
    int n = blockIdx.x, tid = threadIdx.x;
    for (int i = tid; i < CH_STRIDE; i += blockDim.x) s_in[i] = 0.f;
    for (int idx = tid; idx < CC * 9; idx += blockDim.x) {
        int o = idx / 9, k = idx % 9;
        s_w[k * CC + o] = w[idx];
    }
    __syncthreads();
    const float* inb = in + (size_t)n * NPIX;
    for (int p = tid; p < NPIX; p += blockDim.x) {
        int y = p / 33, x = p - y * 33;
        s_in[(y + 1) * PADS + x + 1] = inb[p];
    }
    __syncthreads();
    float* outb = out + (size_t)n * CC * NPIX;
    for (int p = tid; p < NPIX; p += blockDim.x) {
        int y = p / 33, x = p - y * 33;
        float acc[CC];
        #pragma unroll
        for (int co = 0; co < CC; co++) acc[co] = 0.f;
        const float* sp = s_in + y * PADS + x;
        #pragma unroll
        for (int k = 0; k < 9; k++) {
            float v = sp[(k / 3) * PADS + (k % 3)];
            #pragma unroll
            for (int co = 0; co < CC; co++)
                acc[co] = fmaf(v, s_w[k * CC + co], acc[co]);
        }
        #pragma unroll
        for (int co = 0; co < CC; co++) outb[co * NPIX + p] = acc[co];
    }
}

// ---------------- heavy 32->32 3x3 conv (fwd or transposed) ----------------
// flags: FLAG_ACT_IN = apply act() while staging input;
//        FLAG_FLIP   = use flipped/transposed weights (conv_transpose);
//        FLAG_ACTDER = multiply output by actdf(pre) elementwise.
__global__ __launch_bounds__(CONV_THREADS, 1) void k_conv(
        const float* __restrict__ in, const float* __restrict__ w,
        float* __restrict__ out, const float* __restrict__ pre, int flags) {
    extern __shared__ float smem[];
    float* s_in = smem;                    // CC * CH_STRIDE
    float* s_w  = smem + CC * CH_STRIDE;   // [ci][k][co]
    int n = blockIdx.x, tid = threadIdx.x;

    for (int i = tid; i < CC * CH_STRIDE; i += blockDim.x) s_in[i] = 0.f;
    for (int idx = tid; idx < CC * CC * 9; idx += blockDim.x) {
        int kx = idx % 3, ky = (idx / 3) % 3;
        int i = (idx / 9) % CC, o = idx / (9 * CC);
        float v = w[idx];
        int eci, eco, ek;
        if (flags & FLAG_FLIP) { eci = o; eco = i; ek = (2 - ky) * 3 + (2 - kx); }
        else                   { eci = i; eco = o; ek = ky * 3 + kx; }
        s_w[(eci * 9 + ek) * CC + eco] = v;
    }
    __syncthreads();
    const float* inb = in + (size_t)n * CC * NPIX;
    bool act_in = (flags & FLAG_ACT_IN) != 0;
    for (int idx = tid; idx < CC * NPIX; idx += blockDim.x) {
        int ci = idx / NPIX, p = idx - ci * NPIX;
        int y = p / 33, x = p - y * 33;
        float v = inb[idx];
        if (act_in) v = actf(v);
        s_in[ci * CH_STRIDE + (y + 1) * PADS + (x + 1)] = v;
    }
    __syncthreads();

    const float* preb = pre + (size_t)n * CC * NPIX;
    float* outb = out + (size_t)n * CC * NPIX;
    bool actder = (flags & FLAG_ACTDER) != 0;

    for (int p = tid; p < NPIX; p += blockDim.x) {
        int y = p / 33, x = p - y * 33;
        float acc[CC];
        #pragma unroll
        for (int co = 0; co < CC; co++) acc[co] = 0.f;
        const float* sbase = s_in + y * PADS + x;
        for (int ci = 0; ci < CC; ci++) {
            const float* sp = sbase + ci * CH_STRIDE;
            const float* wp = s_w + ci * 9 * CC;
            #pragma unroll
            for (int k = 0; k < 9; k++) {
                float v = sp[(k / 3) * PADS + (k % 3)];
                #pragma unroll
                for (int co = 0; co < CC; co++)
                    acc[co] = fmaf(v, wp[k * CC + co], acc[co]);
            }
        }
        if (actder) {
            #pragma unroll
            for (int co = 0; co < CC; co++)
                acc[co] *= actdf(preb[co * NPIX + p]);
        }
        #pragma unroll
        for (int co = 0; co < CC; co++) outb[co * NPIX + p] = acc[co];
    }
}

// ---------------- g_factor (gradient-field normalization) ----------------
__global__ void k_gfactor(float* __restrict__ g, const float* __restrict__ soft_thr) {
    int n = blockIdx.x;
    float thr = soft_thr[0] * d_gamma;
    float inv_thr = 1.0f / thr;
    float* gb = g + (size_t)n * CC * NPIX;
    for (int p = threadIdx.x; p < NPIX; p += blockDim.x) {
        float v[CC];
        float s = 0.f;
        #pragma unroll
        for (int c = 0; c < CC; c++) { v[c] = gb[c * NPIX + p]; s = fmaf(v[c], v[c], s); }
        float nrm = sqrtf(s);
        float f = (nrm > thr) ? (1.0f / fmaxf(nrm, 1e-12f)) : inv_thr;
        #pragma unroll
        for (int c = 0; c < CC; c++) gb[c * NPIX + p] = v[c] * f;
    }
}

// ---------------- convT1 (32 -> 1), fused with x/gphi update ----------------
// mode 0: x = z - tau * gr   (tau = |a|*|b|/(|a|+|b|)), optionally mirrored to out_extra
// mode 1: gphi += gr
__global__ __launch_bounds__(CONV_THREADS, 1) void k_convT1(
        const float* __restrict__ in, const float* __restrict__ w1,
        const float* __restrict__ z, float* __restrict__ x, float* __restrict__ gphi,
        const float* __restrict__ alphas, const float* __restrict__ betas,
        int phase, int mode, float* __restrict__ out_extra) {
    extern __shared__ float smem[];
    float* s_in = smem;                 // CC * CH_STRIDE
    __shared__ float s_w[CC * 9];       // flipped [o][k]
    int n = blockIdx.x, tid = threadIdx.x;
    for (int i = tid; i < CC * CH_STRIDE; i += blockDim.x) s_in[i] = 0.f;
    for (int idx = tid; idx < CC * 9; idx += blockDim.x) {
        int o = idx / 9, k = idx % 9;
        int ky = k / 3, kx = k % 3;
        s_w[o * 9 + (2 - ky) * 3 + (2 - kx)] = w1[idx];
    }
    __syncthreads();
    const float* inb = in + (size_t)n * CC * NPIX;
    for (int idx = tid; idx < CC * NPIX; idx += blockDim.x) {
        int ci = idx / NPIX, p = idx - ci * NPIX;
        int y = p / 33, x2 = p - y * 33;
        s_in[ci * CH_STRIDE + (y + 1) * PADS + (x2 + 1)] = inb[idx];
    }
    __syncthreads();

    float a = fabsf(alphas[phase]), b = fabsf(betas[phase]);
    float tau = a * b / (a + b);

    for (int p = tid; p < NPIX; p += blockDim.x) {
        int y = p / 33, xx = p - y * 33;
        float acc = 0.f;
        const float* sbase = s_in + y * PADS + xx;
        for (int o = 0; o < CC; o++) {
            const float* sp = sbase + o * CH_STRIDE;
            const float* wp = s_w + o * 9;
            #pragma unroll
            for (int k = 0; k < 9; k++)
                acc = fmaf(sp[(k / 3) * PADS + (k % 3)], wp[k], acc);
        }
        size_t off = (size_t)n * NPIX + p;
        if (mode == 0) {
            float nx = z[off] - tau * acc;
            x[off] = nx;
            if (out_extra) out_extra[off] = nx;
        } else {
            gphi[off] += acc;
        }
    }
}

// ---------------- row norms + gamma update ----------------
__global__ void k_rownorm(const float* __restrict__ gphi) {
    __shared__ float red[256];
    int bidx = blockIdx.x;
    float s = 0.f;
    for (int j = threadIdx.x; j < NPIX; j += 256) {
        float v = gphi[(size_t)bidx * NPIX + j];
        s = fmaf(v, v, s);
    }
    red[threadIdx.x] = s;
    __syncthreads();
    for (int off = 128; off > 0; off >>= 1) {
        if (threadIdx.x < off) red[threadIdx.x] += red[threadIdx.x + off];
        __syncthreads();
    }
    if (threadIdx.x == 0) d_ngrad[bidx] = sqrtf(red[0]);
}

__global__ void k_gamma(const float* __restrict__ soft_thr) {
    __shared__ float red[256];
    red[threadIdx.x] = d_ngrad[threadIdx.x];
    __syncthreads();
    for (int off = 128; off > 0; off >>= 1) {
        if (threadIdx.x < off) red[threadIdx.x] += red[threadIdx.x + off];
        __syncthreads();
    }
    if (threadIdx.x == 0) {
        float mean = red[0] / (float)BB;
        float g = d_gamma;
        if (mean < 15000.0f * g * soft_thr[0]) g *= 0.9f;
        d_gamma = g;
    }
}

// ---------------- host orchestration ----------------
#define SMEM_CONV ((CC * CH_STRIDE + CC * CC * 9) * (int)sizeof(float))   /* 198144 */
#define SMEM_T1   ((CC * CH_STRIDE) * (int)sizeof(float))                 /* 161280 */

static void grad_r_chain(const float* src, const float* c1, const float* c2,
                         const float* c3, const float* c4, const float* soft,
                         float* px1, float* px2, float* px3, float* pg, float* pbA,
                         const float* pz, float* px, float* pgphi,
                         const float* alphas, const float* betas,
                         int phase, int mode, float* out_extra) {
    k_conv1<<<BB, CONV_THREADS>>>(src, c1, px1);
    k_conv<<<BB, CONV_THREADS, SMEM_CONV>>>(px1, c2, px2, px1, FLAG_ACT_IN);
    k_conv<<<BB, CONV_THREADS, SMEM_CONV>>>(px2, c3, px3, px1, FLAG_ACT_IN);
    k_conv<<<BB, CONV_THREADS, SMEM_CONV>>>(px3, c4, pg,  px1, FLAG_ACT_IN);
    k_gfactor<<<BB, 256>>>(pg, soft);
    k_conv<<<BB, CONV_THREADS, SMEM_CONV>>>(pg,  c4, pbA, px3, FLAG_FLIP | FLAG_ACTDER);
    k_conv<<<BB, CONV_THREADS, SMEM_CONV>>>(pbA, c3, pg,  px2, FLAG_FLIP | FLAG_ACTDER);
    k_conv<<<BB, CONV_THREADS, SMEM_CONV>>>(pg,  c2, pbA, px1, FLAG_FLIP | FLAG_ACTDER);
    k_convT1<<<BB, CONV_THREADS, SMEM_T1>>>(pbA, c1, pz, px, pgphi,
                                            alphas, betas, phase, mode, out_extra);
}

extern "C" void kernel_launch(void* const* d_in, const int* in_sizes, int n_in,
                              void* d_out, int out_size) {
    (void)in_sizes; (void)n_in; (void)out_size;
    const float* Phix   = (const float*)d_in[0];
    const float* Phi    = (const float*)d_in[1];
    const float* Qinit  = (const float*)d_in[2];
    const float* soft   = (const float*)d_in[3];
    const float* alphas = (const float*)d_in[4];
    const float* betas  = (const float*)d_in[5];
    const float* c1     = (const float*)d_in[6];
    const float* c2     = (const float*)d_in[7];
    const float* c3     = (const float*)d_in[8];
    const float* c4     = (const float*)d_in[9];
    float* out = (float*)d_out;

    cudaFuncSetAttribute(k_conv,   cudaFuncAttributeMaxDynamicSharedMemorySize, SMEM_CONV);
    cudaFuncSetAttribute(k_convT1, cudaFuncAttributeMaxDynamicSharedMemorySize, SMEM_T1);

    float *px, *pz, *pgphi, *px1, *px2, *px3, *pg, *pbA, *pPhiTb;
    cudaGetSymbolAddress((void**)&px,     d_x);
    cudaGetSymbolAddress((void**)&pz,     d_z);
    cudaGetSymbolAddress((void**)&pgphi,  d_gphi);
    cudaGetSymbolAddress((void**)&px1,    d_x1);
    cudaGetSymbolAddress((void**)&px2,    d_x2);
    cudaGetSymbolAddress((void**)&px3,    d_x3);
    cudaGetSymbolAddress((void**)&pg,     d_g);
    cudaGetSymbolAddress((void**)&pbA,    d_bA);
    cudaGetSymbolAddress((void**)&pPhiTb, d_PhiTb);

    dim3 tb(16, 16);
    k_init_gamma<<<1, 1>>>();
    k_phitphi<<<dim3(35, 35), tb>>>(Phi);
    k_setup<<<dim3(35, 8), tb>>>(Phix, Phi,   pPhiTb, 0);  // PhiTb = Phix @ Phi
    k_setup<<<dim3(35, 8), tb>>>(Phix, Qinit, px,     1);  // x0 = Phix @ Qinit^T

    for (int p = 0; p < 3; p++) {
        // z = x - alpha*(x @ P) + alpha*PhiTb
        k_gemm_phase<<<dim3(35, 8), tb>>>(px, pz, alphas, p, 0);
        // x = z - tau * grad_r(z); final phase mirrors x into d_out
        grad_r_chain(pz, c1, c2, c3, c4, soft, px1, px2, px3, pg, pbA,
                     pz, px, pgphi, alphas, betas, p, 0,
                     (p == 2) ? out : nullptr);
        if (p < 2) {
            // gphi = x @ P - PhiTb + grad_r(x); then gamma update
            k_gemm_phase<<<dim3(35, 8), tb>>>(px, pgphi, alphas, p, 1);
            grad_r_chain(px, c1, c2, c3, c4, soft, px1, px2, px3, pg, pbA,
                         pz, px, pgphi, alphas, betas, p, 1, nullptr);
            k_rownorm<<<BB, 256>>>(pgphi);
            k_gamma<<<1, 256>>>(soft);
        }
    }
}

// round 2
// speedup vs baseline: 1.1376x; 1.1376x over previous
#include <cuda_runtime.h>
#include <math.h>

#define BB   256
#define NPIX 1089
#define WDIM 33
#define MDIM 272
#define CC   32
#define PADS 36
#define CH_STRIDE (35*PADS)   /* 1260 floats per padded channel */
#define CONV_THREADS 288
#define NPAIR 545             /* ceil(1089/2) pixel pairs */

#define FLAG_ACT_IN 1
#define FLAG_FLIP   2
#define FLAG_ACTDER 4
#define FLAG_GNORM  8

typedef unsigned long long u64;

// ---------------- device state (static, no allocation) ----------------
__device__ float d_P[NPIX*NPIX];
__device__ float d_PhiTb[BB*NPIX];
__device__ float d_x[BB*NPIX];
__device__ float d_z[BB*NPIX];
__device__ float d_gphi[BB*NPIX];
__device__ float d_dotm[BB*NPIX];
__device__ float d_x1[BB*CC*NPIX];
__device__ float d_x2[BB*CC*NPIX];
__device__ float d_x3[BB*CC*NPIX];
__device__ float d_g [BB*CC*NPIX];
__device__ float d_bA[BB*CC*NPIX];
__device__ float d_ngrad[BB];
__device__ float d_gamma;

// ---------------- packed f32x2 helpers ----------------
__device__ __forceinline__ u64 pk2(float a, float b) {
    u64 r; asm("mov.b64 %0, {%1,%2};" : "=l"(r) : "f"(a), "f"(b)); return r;
}
__device__ __forceinline__ void fma2(u64& d, u64 a, u64 b) {
    asm("fma.rn.f32x2 %0, %1, %2, %3;" : "=l"(d) : "l"(a), "l"(b), "l"(d));
}
__device__ __forceinline__ float2 upk2(u64 v) {
    float2 f; asm("mov.b64 {%0,%1}, %2;" : "=f"(f.x), "=f"(f.y) : "l"(v)); return f;
}

// ---------------- activation (eq. 33), DELTA = 0.01 ----------------
__device__ __forceinline__ float actf(float v) {
    if (fabsf(v) > 0.01f) return fmaxf(v, 0.0f);
    return fmaf(v*v, 25.0f, fmaf(v, 0.5f, 0.0025f));
}
__device__ __forceinline__ float actdf(float v) {
    if (fabsf(v) > 0.01f) return v > 0.0f ? 1.0f : 0.0f;
    return fmaf(v, 50.0f, 0.5f);
}

__global__ void k_init_gamma() { d_gamma = 1.0f; }

// ---------------- GEMM: P = Phi^T Phi (64x64 tiles, 4x4 per thread) ----------------
__global__ void k_phitphi64(const float* __restrict__ Phi) {
    __shared__ float As[16][68];
    __shared__ float Bs[16][68];
    int ib = blockIdx.y * 64, jb = blockIdx.x * 64;
    int tx = threadIdx.x, ty = threadIdx.y;
    int t = ty * 16 + tx;
    float acc[4][4];
    #pragma unroll
    for (int r = 0; r < 4; r++)
        #pragma unroll
        for (int c = 0; c < 4; c++) acc[r][c] = 0.f;

    for (int k0 = 0; k0 < MDIM; k0 += 16) {   // 272 = 17*16 exact
        #pragma unroll
        for (int q = t; q < 1024; q += 256) {
            int kk = q / 64, r = q % 64;
            As[kk][r] = (ib + r < NPIX) ? Phi[(k0 + kk) * NPIX + ib + r] : 0.f;
            Bs[kk][r] = (jb + r < NPIX) ? Phi[(k0 + kk) * NPIX + jb + r] : 0.f;
        }
        __syncthreads();
        #pragma unroll
        for (int kk = 0; kk < 16; kk++) {
            float4 a4 = *(const float4*)&As[kk][ty * 4];
            float4 b4 = *(const float4*)&Bs[kk][tx * 4];
            float ar[4] = {a4.x, a4.y, a4.z, a4.w};
            float br[4] = {b4.x, b4.y, b4.z, b4.w};
            #pragma unroll
            for (int r = 0; r < 4; r++)
                #pragma unroll
                for (int c = 0; c < 4; c++)
                    acc[r][c] = fmaf(ar[r], br[c], acc[r][c]);
        }
        __syncthreads();
    }
    #pragma unroll
    for (int r = 0; r < 4; r++) {
        int i = ib + ty * 4 + r;
        if (i >= NPIX) continue;
        #pragma unroll
        for (int c = 0; c < 4; c++) {
            int j = jb + tx * 4 + c;
            if (j < NPIX) d_P[i * NPIX + j] = acc[r][c];
        }
    }
}

// ---------------- phase GEMM: dot = src @ P  (64x64, 4x4) ----------------
// mode 0 (Z):    dst = src + |alphas[p]|*(PhiTb - dot)
// mode 1 (DOTM): dst = dot - PhiTb
__global__ void k_gemmP(const float* __restrict__ src, float* __restrict__ dst,
                        const float* __restrict__ alphas, int phase, int mode) {
    __shared__ float As[16][68];
    __shared__ float Bs[16][68];
    int bb = blockIdx.y * 64, jb = blockIdx.x * 64;
    int tx = threadIdx.x, ty = threadIdx.y;
    int t = ty * 16 + tx;
    float acc[4][4];
    #pragma unroll
    for (int r = 0; r < 4; r++)
        #pragma unroll
        for (int c = 0; c < 4; c++) acc[r][c] = 0.f;

    for (int k0 = 0; k0 < NPIX; k0 += 16) {
        #pragma unroll
        for (int q = t; q < 1024; q += 256) {
            int r = q / 16, kk = q % 16;
            As[kk][r] = (k0 + kk < NPIX) ? src[(bb + r) * NPIX + k0 + kk] : 0.f;
        }
        #pragma unroll
        for (int q = t; q < 1024; q += 256) {
            int kk = q / 64, c = q % 64;
            Bs[kk][c] = (k0 + kk < NPIX && jb + c < NPIX) ? d_P[(k0 + kk) * NPIX + jb + c] : 0.f;
        }
        __syncthreads();
        #pragma unroll
        for (int kk = 0; kk < 16; kk++) {
            float4 a4 = *(const float4*)&As[kk][ty * 4];
            float4 b4 = *(const float4*)&Bs[kk][tx * 4];
            float ar[4] = {a4.x, a4.y, a4.z, a4.w};
            float br[4] = {b4.x, b4.y, b4.z, b4.w};
            #pragma unroll
            for (int r = 0; r < 4; r++)
                #pragma unroll
                for (int c = 0; c < 4; c++)
                    acc[r][c] = fmaf(ar[r], br[c], acc[r][c]);
        }
        __syncthreads();
    }
    float alpha = fabsf(alphas[phase]);
    #pragma unroll
    for (int r = 0; r < 4; r++) {
        int b = bb + ty * 4 + r;
        #pragma unroll
        for (int c = 0; c < 4; c++) {
            int j = jb + tx * 4 + c;
            if (j < NPIX) {
                float dot = acc[r][c];
                float ptb = d_PhiTb[b * NPIX + j];
                if (mode == 0)
                    dst[b * NPIX + j] = src[b * NPIX + j] + alpha * (ptb - dot);
                else
                    dst[b * NPIX + j] = dot - ptb;
            }
        }
    }
}

// ---------------- z step (reuse stored dotm): z = x - |alpha|*dotm ----------------
__global__ void k_zstep(const float* __restrict__ x, float* __restrict__ z,
                        const float* __restrict__ alphas, int phase) {
    float alpha = fabsf(alphas[phase]);
    size_t base = (size_t)blockIdx.x * NPIX;
    for (int j = threadIdx.x; j < NPIX; j += blockDim.x)
        z[base + j] = x[base + j] - alpha * d_dotm[base + j];
}

// ---------------- setup GEMMs: dst[b,j] = sum_m Phix[b,m]*B(m,j) ----------------
__global__ void k_setup(const float* __restrict__ Phix, const float* __restrict__ Bsrc,
                        float* __restrict__ dst, int tmode) {
    __shared__ float As[32][33];
    __shared__ float Bs[32][33];
    int bb = blockIdx.y * 32, jb = blockIdx.x * 32;
    int tx = threadIdx.x, ty = threadIdx.y;
    int t = ty * 16 + tx;
    float acc00 = 0.f, acc01 = 0.f, acc10 = 0.f, acc11 = 0.f;
    for (int k0 = 0; k0 < MDIM; k0 += 32) {
        for (int q = t; q < 1024; q += 256) {
            int kk = q % 32, r = q / 32;
            As[kk][r] = (k0 + kk < MDIM) ? Phix[(bb + r) * MDIM + k0 + kk] : 0.f;
        }
        if (tmode == 0) {
            for (int q = t; q < 1024; q += 256) {
                int kk = q / 32, j = q % 32;
                Bs[kk][j] = (k0 + kk < MDIM && jb + j < NPIX) ? Bsrc[(k0 + kk) * NPIX + jb + j] : 0.f;
            }
        } else {
            for (int q = t; q < 1024; q += 256) {
                int kk = q % 32, j = q / 32;
                Bs[kk][j] = (k0 + kk < MDIM && jb + j < NPIX) ? Bsrc[(jb + j) * MDIM + k0 + kk] : 0.f;
            }
        }
        __syncthreads();
        #pragma unroll
        for (int kk = 0; kk < 32; kk++) {
            float a0 = As[kk][ty*2], a1 = As[kk][ty*2+1];
            float b0 = Bs[kk][tx*2], b1 = Bs[kk][tx*2+1];
            acc00 = fmaf(a0, b0, acc00); acc01 = fmaf(a0, b1, acc01);
            acc10 = fmaf(a1, b0, acc10); acc11 = fmaf(a1, b1, acc11);
        }
        __syncthreads();
    }
    int b0 = bb + ty*2, j0 = jb + tx*2;
    if (j0     < NPIX) dst[(b0  ) * NPIX + j0  ] = acc00;
    if (j0 + 1 < NPIX) dst[(b0  ) * NPIX + j0+1] = acc01;
    if (j0     < NPIX) dst[(b0+1) * NPIX + j0  ] = acc10;
    if (j0 + 1 < NPIX) dst[(b0+1) * NPIX + j0+1] = acc11;
}

// ---------------- conv1 forward: [B,1,33,33] -> [B,32,33,33] ----------------
__global__ __launch_bounds__(CONV_THREADS) void k_conv1(
        const float* __restrict__ in, const float* __restrict__ w,
        float* __restrict__ out) {
    __shared__ float s_in[CH_STRIDE];
    __shared__ float s_w[9 * CC];       // [k][co]
    int n = blockIdx.x, tid = threadIdx.x;
    for (int i = tid; i < CH_STRIDE; i += blockDim.x) s_in[i] = 0.f;
    for (int idx = tid; idx < CC * 9; idx += blockDim.x) {
        int o = idx / 9, k = idx % 9;
        s_w[k * CC + o] = w[idx];
    }
    __syncthreads();
    const float* inb = in + (size_t)n * NPIX;
    for (int p = tid; p < NPIX; p += blockDim.x) {
        int y = p / 33, x = p - y * 33;
        s_in[(y + 1) * PADS + x + 1] = inb[p];
    }
    __syncthreads();
    float* outb = out + (size_t)n * CC * NPIX;
    for (int p = tid; p < NPIX; p += blockDim.x) {
        int y = p / 33, x = p - y * 33;
        float acc[CC];
        #pragma unroll
        for (int co = 0; co < CC; co++) acc[co] = 0.f;
        const float* sp = s_in + y * PADS + x;
        #pragma unroll
        for (int k = 0; k < 9; k++) {
            float v = sp[(k / 3) * PADS + (k % 3)];
            #pragma unroll
            for (int co = 0; co < CC; co++)
                acc[co] = fmaf(v, s_w[k * CC + co], acc[co]);
        }
        #pragma unroll
        for (int co = 0; co < CC; co++) outb[co * NPIX + p] = acc[co];
    }
}

// ---------------- heavy 32->32 3x3 conv (fwd or transposed), FFMA2 core ----------------
// flags: FLAG_ACT_IN = apply act() while staging input;
//        FLAG_FLIP   = use flipped/transposed weights (conv_transpose);
//        FLAG_ACTDER = multiply output by actdf(pre) elementwise;
//        FLAG_GNORM  = normalize staged gradient field per pixel (g_factor) first.
__global__ __launch_bounds__(CONV_THREADS, 1) void k_conv(
        const float* __restrict__ in, const float* __restrict__ w,
        float* __restrict__ out, const float* __restrict__ pre,
        const float* __restrict__ soft, int flags) {
    extern __shared__ float smem[];
    float* s_in = smem;                    // CC * CH_STRIDE
    float* s_w  = smem + CC * CH_STRIDE;   // [ci][k][co], co pairs 8B aligned
    int n = blockIdx.x, tid = threadIdx.x;

    for (int i = tid; i < CC * CH_STRIDE; i += blockDim.x) s_in[i] = 0.f;
    for (int idx = tid; idx < CC * CC * 9; idx += blockDim.x) {
        int kx = idx % 3, ky = (idx / 3) % 3;
        int i = (idx / 9) % CC, o = idx / (9 * CC);
        float v = w[idx];
        int eci, eco, ek;
        if (flags & FLAG_FLIP) { eci = o; eco = i; ek = (2 - ky) * 3 + (2 - kx); }
        else                   { eci = i; eco = o; ek = ky * 3 + kx; }
        s_w[(eci * 9 + ek) * CC + eco] = v;
    }
    __syncthreads();
    const float* inb = in + (size_t)n * CC * NPIX;
    bool act_in = (flags & FLAG_ACT_IN) != 0;
    for (int idx = tid; idx < CC * NPIX; idx += blockDim.x) {
        int ci = idx / NPIX, p = idx - ci * NPIX;
        int y = p / 33, x = p - y * 33;
        float v = inb[idx];
        if (act_in) v = actf(v);
        s_in[ci * CH_STRIDE + (y + 1) * PADS + (x + 1)] = v;
    }
    __syncthreads();

    if (flags & FLAG_GNORM) {
        float thr = soft[0] * d_gamma;
        float inv_thr = 1.0f / thr;
        for (int p = tid; p < NPIX; p += blockDim.x) {
            int y = p / 33, x = p - y * 33;
            int off = (y + 1) * PADS + (x + 1);
            float v[CC];
            float s = 0.f;
            #pragma unroll
            for (int c = 0; c < CC; c++) {
                v[c] = s_in[c * CH_STRIDE + off];
                s = fmaf(v[c], v[c], s);
            }
            float nrm = sqrtf(s);
            float f = (nrm > thr) ? (1.0f / fmaxf(nrm, 1e-12f)) : inv_thr;
            #pragma unroll
            for (int c = 0; c < CC; c++) s_in[c * CH_STRIDE + off] = v[c] * f;
        }
        __syncthreads();
    }

    const float* preb = pre + (size_t)n * CC * NPIX;
    float* outb = out + (size_t)n * CC * NPIX;
    bool actder = (flags & FLAG_ACTDER) != 0;

    // 2 pixels per thread; accumulators: 16 co-pairs per pixel, packed f32x2.
    for (int q = tid; q < NPAIR; q += CONV_THREADS) {
        int p0 = 2 * q;
        int p1 = p0 + 1;
        bool ok1 = (p1 < NPIX);
        int p1c = ok1 ? p1 : p0;
        int y0 = p0 / 33, x0 = p0 - y0 * 33;
        int y1 = p1c / 33, x1 = p1c - y1 * 33;

        u64 acc0[16], acc1[16];
        #pragma unroll
        for (int cp = 0; cp < 16; cp++) { acc0[cp] = 0ull; acc1[cp] = 0ull; }

        const float* b0 = s_in + y0 * PADS + x0;
        const float* b1 = s_in + y1 * PADS + x1;
        for (int ci = 0; ci < CC; ci++) {
            const float* sp0 = b0 + ci * CH_STRIDE;
            const float* sp1 = b1 + ci * CH_STRIDE;
            const u64* wp_ci = (const u64*)(s_w + ci * 9 * CC);
            #pragma unroll
            for (int k = 0; k < 9; k++) {
                float v0 = sp0[(k / 3) * PADS + (k % 3)];
                float v1 = sp1[(k / 3) * PADS + (k % 3)];
                u64 vp0 = pk2(v0, v0);
                u64 vp1 = pk2(v1, v1);
                const u64* wp = wp_ci + k * 16;
                #pragma unroll
                for (int cp = 0; cp < 16; cp++) {
                    u64 w2 = wp[cp];
                    fma2(acc0[cp], vp0, w2);
                    fma2(acc1[cp], vp1, w2);
                }
            }
        }

        #pragma unroll
        for (int cp = 0; cp < 16; cp++) {
            float2 a0 = upk2(acc0[cp]);
            int co0 = 2 * cp, co1 = 2 * cp + 1;
            float o00 = a0.x, o01 = a0.y;
            if (actder) {
                o00 *= actdf(preb[co0 * NPIX + p0]);
                o01 *= actdf(preb[co1 * NPIX + p0]);
            }
            outb[co0 * NPIX + p0] = o00;
            outb[co1 * NPIX + p0] = o01;
            if (ok1) {
                float2 a1 = upk2(acc1[cp]);
                float o10 = a1.x, o11 = a1.y;
                if (actder) {
                    o10 *= actdf(preb[co0 * NPIX + p1]);
                    o11 *= actdf(preb[co1 * NPIX + p1]);
                }
                outb[co0 * NPIX + p1] = o10;
                outb[co1 * NPIX + p1] = o11;
            }
        }
    }
}

// ---------------- convT1 (32 -> 1), fused with x/gphi update ----------------
// mode 0: x = z - tau * gr, optionally mirrored to out_extra
// mode 1: gphi = dotm + gr
__global__ __launch_bounds__(CONV_THREADS, 1) void k_convT1(
        const float* __restrict__ in, const float* __restrict__ w1,
        const float* __restrict__ z, float* __restrict__ x,
        const float* __restrict__ dotm, float* __restrict__ gphi,
        const float* __restrict__ alphas, const float* __restrict__ betas,
        int phase, int mode, float* __restrict__ out_extra) {
    extern __shared__ float smem[];
    float* s_in = smem;                 // CC * CH_STRIDE
    __shared__ float s_w[CC * 9];       // flipped [o][k]
    int n = blockIdx.x, tid = threadIdx.x;
    for (int i = tid; i < CC * CH_STRIDE; i += blockDim.x) s_in[i] = 0.f;
    for (int idx = tid; idx < CC * 9; idx += blockDim.x) {
        int o = idx / 9, k = idx % 9;
        int ky = k / 3, kx = k % 3;
        s_w[o * 9 + (2 - ky) * 3 + (2 - kx)] = w1[idx];
    }
    __syncthreads();
    const float* inb = in + (size_t)n * CC * NPIX;
    for (int idx = tid; idx < CC * NPIX; idx += blockDim.x) {
        int ci = idx / NPIX, p = idx - ci * NPIX;
        int y = p / 33, x2 = p - y * 33;
        s_in[ci * CH_STRIDE + (y + 1) * PADS + (x2 + 1)] = inb[idx];
    }
    __syncthreads();

    float a = fabsf(alphas[phase]), b = fabsf(betas[phase]);
    float tau = a * b / (a + b);

    for (int p = tid; p < NPIX; p += blockDim.x) {
        int y = p / 33, xx = p - y * 33;
        float acc = 0.f;
        const float* sbase = s_in + y * PADS + xx;
        for (int o = 0; o < CC; o++) {
            const float* sp = sbase + o * CH_STRIDE;
            const float* wp = s_w + o * 9;
            #pragma unroll
            for (int k = 0; k < 9; k++)
                acc = fmaf(sp[(k / 3) * PADS + (k % 3)], wp[k], acc);
        }
        size_t off = (size_t)n * NPIX + p;
        if (mode == 0) {
            float nx = z[off] - tau * acc;
            x[off] = nx;
            if (out_extra) out_extra[off] = nx;
        } else {
            gphi[off] = dotm[off] + acc;
        }
    }
}

// ---------------- row norms + gamma update ----------------
__global__ void k_rownorm(const float* __restrict__ gphi) {
    __shared__ float red[256];
    int bidx = blockIdx.x;
    float s = 0.f;
    for (int j = threadIdx.x; j < NPIX; j += 256) {
        float v = gphi[(size_t)bidx * NPIX + j];
        s = fmaf(v, v, s);
    }
    red[threadIdx.x] = s;
    __syncthreads();
    for (int off = 128; off > 0; off >>= 1) {
        if (threadIdx.x < off) red[threadIdx.x] += red[threadIdx.x + off];
        __syncthreads();
    }
    if (threadIdx.x == 0) d_ngrad[bidx] = sqrtf(red[0]);
}

__global__ void k_gamma(const float* __restrict__ soft_thr) {
    __shared__ float red[256];
    red[threadIdx.x] = d_ngrad[threadIdx.x];
    __syncthreads();
    for (int off = 128; off > 0; off >>= 1) {
        if (threadIdx.x < off) red[threadIdx.x] += red[threadIdx.x + off];
        __syncthreads();
    }
    if (threadIdx.x == 0) {
        float mean = red[0] / (float)BB;
        float g = d_gamma;
        if (mean < 15000.0f * g * soft_thr[0]) g *= 0.9f;
        d_gamma = g;
    }
}

// ---------------- host orchestration ----------------
#define SMEM_CONV ((CC * CH_STRIDE + CC * CC * 9) * (int)sizeof(float))   /* 198144 */
#define SMEM_T1   ((CC * CH_STRIDE) * (int)sizeof(float))                 /* 161280 */

static void grad_r_chain(const float* src, const float* c1, const float* c2,
                         const float* c3, const float* c4, const float* soft,
                         float* px1, float* px2, float* px3, float* pg, float* pbA,
                         const float* pz, float* px, const float* pdotm, float* pgphi,
                         const float* alphas, const float* betas,
                         int phase, int mode, float* out_extra) {
    k_conv1<<<BB, CONV_THREADS>>>(src, c1, px1);
    k_conv<<<BB, CONV_THREADS, SMEM_CONV>>>(px1, c2, px2, px1, soft, FLAG_ACT_IN);
    k_conv<<<BB, CONV_THREADS, SMEM_CONV>>>(px2, c3, px3, px1, soft, FLAG_ACT_IN);
    k_conv<<<BB, CONV_THREADS, SMEM_CONV>>>(px3, c4, pg,  px1, soft, FLAG_ACT_IN);
    // backward: normalization of g fused into first transposed conv
    k_conv<<<BB, CONV_THREADS, SMEM_CONV>>>(pg,  c4, pbA, px3, soft, FLAG_FLIP | FLAG_ACTDER | FLAG_GNORM);
    k_conv<<<BB, CONV_THREADS, SMEM_CONV>>>(pbA, c3, pg,  px2, soft, FLAG_FLIP | FLAG_ACTDER);
    k_conv<<<BB, CONV_THREADS, SMEM_CONV>>>(pg,  c2, pbA, px1, soft, FLAG_FLIP | FLAG_ACTDER);
    k_convT1<<<BB, CONV_THREADS, SMEM_T1>>>(pbA, c1, pz, px, pdotm, pgphi,
                                            alphas, betas, phase, mode, out_extra);
}

extern "C" void kernel_launch(void* const* d_in, const int* in_sizes, int n_in,
                              void* d_out, int out_size) {
    (void)in_sizes; (void)n_in; (void)out_size;
    const float* Phix   = (const float*)d_in[0];
    const float* Phi    = (const float*)d_in[1];
    const float* Qinit  = (const float*)d_in[2];
    const float* soft   = (const float*)d_in[3];
    const float* alphas = (const float*)d_in[4];
    const float* betas  = (const float*)d_in[5];
    const float* c1     = (const float*)d_in[6];
    const float* c2     = (const float*)d_in[7];
    const float* c3     = (const float*)d_in[8];
    const float* c4     = (const float*)d_in[9];
    float* out = (float*)d_out;

    cudaFuncSetAttribute(k_conv,   cudaFuncAttributeMaxDynamicSharedMemorySize, SMEM_CONV);
    cudaFuncSetAttribute(k_convT1, cudaFuncAttributeMaxDynamicSharedMemorySize, SMEM_T1);

    float *px, *pz, *pgphi, *pdotm, *px1, *px2, *px3, *pg, *pbA, *pPhiTb;
    cudaGetSymbolAddress((void**)&px,     d_x);
    cudaGetSymbolAddress((void**)&pz,     d_z);
    cudaGetSymbolAddress((void**)&pgphi,  d_gphi);
    cudaGetSymbolAddress((void**)&pdotm,  d_dotm);
    cudaGetSymbolAddress((void**)&px1,    d_x1);
    cudaGetSymbolAddress((void**)&px2,    d_x2);
    cudaGetSymbolAddress((void**)&px3,    d_x3);
    cudaGetSymbolAddress((void**)&pg,     d_g);
    cudaGetSymbolAddress((void**)&pbA,    d_bA);
    cudaGetSymbolAddress((void**)&pPhiTb, d_PhiTb);

    dim3 tb16(16, 16);
    k_init_gamma<<<1, 1>>>();
    k_phitphi64<<<dim3(18, 18), tb16>>>(Phi);
    k_setup<<<dim3(35, 8), tb16>>>(Phix, Phi,   pPhiTb, 0);  // PhiTb = Phix @ Phi
    k_setup<<<dim3(35, 8), tb16>>>(Phix, Qinit, px,     1);  // x0 = Phix @ Qinit^T

    for (int p = 0; p < 3; p++) {
        // z = x - alpha*(x@P - PhiTb): full GEMM only for phase 0; later phases
        // reuse dotm computed during the previous phase's gphi step.
        if (p == 0)
            k_gemmP<<<dim3(18, 4), tb16>>>(px, pz, alphas, p, 0);
        else
            k_zstep<<<BB, 256>>>(px, pz, alphas, p);
        // x = z - tau * grad_r(z); final phase mirrors x into d_out
        grad_r_chain(pz, c1, c2, c3, c4, soft, px1, px2, px3, pg, pbA,
                     pz, px, pdotm, pgphi, alphas, betas, p, 0,
                     (p == 2) ? out : nullptr);
        if (p < 2) {
            // dotm = x@P - PhiTb (kept for next phase's z); gphi = dotm + grad_r(x)
            k_gemmP<<<dim3(18, 4), tb16>>>(px, pdotm, alphas, p, 1);
            grad_r_chain(px, c1, c2, c3, c4, soft, px1, px2, px3, pg, pbA,
                         pz, px, pdotm, pgphi, alphas, betas, p, 1, nullptr);
            k_rownorm<<<BB, 256>>>(pgphi);
            k_gamma<<<1, 256>>>(soft);
        }
    }
}